// round 8
// baseline (speedup 1.0000x reference)
#include <cuda_runtime.h>
#include <cuda_bf16.h>
#include <mma.h>
#include <cstdint>

using namespace nvcuda;

#define OBS 194
#define HID 64
#define NACT 5
#define TM 128
#define NTHR 512
#define GRID 152

// ---------------- global weight scratch (bf16 hi/lo, written by setup kernel) ----------------
__device__ __nv_bfloat16 g_b1hi[208 * 128];   // [K=208][N=128], ld 128
__device__ __nv_bfloat16 g_b1lo[208 * 128];
__device__ __nv_bfloat16 g_b2hi[2 * 64 * 64]; // [half][K=64][N=64], ld 64
__device__ __nv_bfloat16 g_b2lo[2 * 64 * 64];

// ---------------- SMEM layout (bytes) ----------------
#define LDXA 216     // x staged bf16, [128][216] (208 K cols + pad)
#define LDA2 136     // feat bf16 [128][136]
#define LDCS 136     // C scratch float [128][136]
#define XAHI_OFF 0          // 128*216*2 = 55296 ; A2HI reuses this region (34816)
#define XALO_OFF 55296      // 55296      ; A2LO reuses this region
#define CSCR_OFF 110592     // 128*136*4 = 69632
#define WHS_OFF  180224     // 960 floats
#define B1S_OFF  184064     // 128 floats
#define B2S_OFF  184576     // 128 floats
#define WC3S_OFF 185088     // 64 floats
#define BHS_OFF  185344     // 16 floats
#define BC3S_OFF 185408     // 1 float
#define SMEM_BYTES 185472

static __device__ __forceinline__ float tanh_fast(float x) {
    float y;
    asm("tanh.approx.f32 %0, %1;" : "=f"(y) : "f"(x));
    return y;
}
static __device__ __forceinline__ void split2(float v, __nv_bfloat16& h, __nv_bfloat16& l) {
    h = __float2bfloat16(v);
    l = __float2bfloat16(v - __bfloat162float(h));
}

// ---------------- setup: convert weights to pre-split bf16 ----------------
__global__ void wconv_kernel(const float* __restrict__ W1, const float* __restrict__ Wc1,
                             const float* __restrict__ W2, const float* __restrict__ Wc2)
{
    const int stride = gridDim.x * blockDim.x;
    const int t0 = blockIdx.x * blockDim.x + threadIdx.x;
    for (int i = t0; i < 208 * 128; i += stride) {
        int k = i >> 7, n = i & 127;
        float v = 0.f;
        if (k < OBS) v = (n < 64) ? W1[k * 64 + n] : Wc1[k * 64 + (n - 64)];
        __nv_bfloat16 h, l; split2(v, h, l);
        g_b1hi[i] = h; g_b1lo[i] = l;
    }
    for (int i = t0; i < 2 * 64 * 64; i += stride) {
        int half = i >> 12, k = (i >> 6) & 63, n = i & 63;
        float v = half ? Wc2[k * 64 + n] : W2[k * 64 + n];
        __nv_bfloat16 h, l; split2(v, h, l);
        g_b2hi[i] = h; g_b2lo[i] = l;
    }
}

// ---------------- main: persistent tiles ----------------
__global__ void __launch_bounds__(NTHR, 1)
agent_pers_kernel(const float* __restrict__ x, const int* __restrict__ action,
                  const float* __restrict__ b1, const float* __restrict__ b2,
                  const float* __restrict__ Wh, const float* __restrict__ bh,
                  const float* __restrict__ bc1, const float* __restrict__ bc2,
                  const float* __restrict__ Wc3, const float* __restrict__ bc3,
                  float* __restrict__ out, int B, int ntiles)
{
    extern __shared__ char smem[];
    __nv_bfloat16* xahi = (__nv_bfloat16*)(smem + XAHI_OFF);
    __nv_bfloat16* xalo = (__nv_bfloat16*)(smem + XALO_OFF);
    __nv_bfloat16* a2hi = (__nv_bfloat16*)(smem + XAHI_OFF);  // reuse after GEMM1
    __nv_bfloat16* a2lo = (__nv_bfloat16*)(smem + XALO_OFF);
    float* cscr = (float*)(smem + CSCR_OFF);
    float* whs  = (float*)(smem + WHS_OFF);
    float* b1s  = (float*)(smem + B1S_OFF);
    float* b2s  = (float*)(smem + B2S_OFF);
    float* wc3s = (float*)(smem + WC3S_OFF);
    float* bhs  = (float*)(smem + BHS_OFF);
    float* bc3s = (float*)(smem + BC3S_OFF);

    const int tid = threadIdx.x;
    const int wid = tid >> 5;

    // stage small constants once per CTA
    if (tid < 64) {
        b1s[tid] = b1[tid];  b1s[64 + tid] = bc1[tid];
        b2s[tid] = b2[tid];  b2s[64 + tid] = bc2[tid];
        wc3s[tid] = Wc3[tid];
    }
    for (int i = tid; i < 3 * HID * NACT; i += NTHR) whs[i] = Wh[i];
    if (tid < 3 * NACT) bhs[tid] = bh[tid];
    if (tid == 0) bc3s[0] = bc3[0];
    // (first __syncthreads inside the tile loop covers this staging)

    const int wn   = (wid & 8) ? 64 : 0;   // N-column half handled by this warp
    const int wrow = (wid & 7) * 16;       // row stripe
    const int whalf = (wid & 8) ? 1 : 0;

    wmma::fragment<wmma::matrix_a, 16, 16, 16, __nv_bfloat16, wmma::row_major> af;
    wmma::fragment<wmma::matrix_b, 16, 16, 16, __nv_bfloat16, wmma::row_major> bf;
    wmma::fragment<wmma::accumulator, 16, 16, 16, float> acc[4];

    for (int tile = blockIdx.x; tile < ntiles; tile += gridDim.x) {
        const int b0 = tile * TM;

        // ---- stage x tile: float -> bf16 hi/lo, [128][216] ----
        for (int i = tid; i < 128 * 108; i += NTHR) {
            int row = i / 108;
            int col = (i - row * 108) * 2;
            int gb  = b0 + row;
            float f0 = 0.f, f1 = 0.f;
            if (gb < B && col < OBS) {
                float2 t = *(const float2*)(x + (size_t)gb * OBS + col);
                f0 = t.x; f1 = t.y;
            }
            __nv_bfloat16 h0, l0, h1, l1;
            split2(f0, h0, l0); split2(f1, h1, l1);
            *(__nv_bfloat162*)(xahi + row * LDXA + col) = __nv_bfloat162(h0, h1);
            *(__nv_bfloat162*)(xalo + row * LDXA + col) = __nv_bfloat162(l0, l1);
        }
        __syncthreads();

        // ---- GEMM1: C1 = Xsplit[128x208] @ B1[208x128], 3-term split, B from gmem ----
        #pragma unroll
        for (int j = 0; j < 4; j++) wmma::fill_fragment(acc[j], 0.0f);
        #pragma unroll
        for (int p = 0; p < 3; p++) {
            const __nv_bfloat16* As = (p < 2) ? xahi : xalo;
            const __nv_bfloat16* Bg = (p == 1) ? g_b1lo : g_b1hi;
            for (int kt = 0; kt < 13; kt++) {
                wmma::load_matrix_sync(af, As + wrow * LDXA + kt * 16, LDXA);
                #pragma unroll
                for (int j = 0; j < 4; j++) {
                    wmma::load_matrix_sync(bf, Bg + (kt * 16) * 128 + wn + j * 16, 128);
                    wmma::mma_sync(acc[j], af, bf, acc[j]);
                }
            }
        }
        // store C1 (float) to scratch
        #pragma unroll
        for (int j = 0; j < 4; j++)
            wmma::store_matrix_sync(cscr + wrow * LDCS + wn + j * 16, acc[j], LDCS, wmma::mem_row_major);
        __syncthreads();

        // ---- epilogue1: h1 = tanh(C1 + bias1) -> A2 hi/lo (overwrites x region) ----
        for (int i = tid; i < 128 * 128; i += NTHR) {
            int row = i >> 7, col = i & 127;
            float f = tanh_fast(cscr[row * LDCS + col] + b1s[col]);
            __nv_bfloat16 h, l; split2(f, h, l);
            a2hi[row * LDA2 + col] = h;
            a2lo[row * LDA2 + col] = l;
        }
        __syncthreads();

        // ---- GEMM2 (block-diagonal): actor warps K=0..63, critic warps K=64..127 ----
        #pragma unroll
        for (int j = 0; j < 4; j++) wmma::fill_fragment(acc[j], 0.0f);
        #pragma unroll
        for (int p = 0; p < 3; p++) {
            const __nv_bfloat16* As = (p < 2) ? a2hi : a2lo;
            const __nv_bfloat16* Bg = ((p == 1) ? g_b2lo : g_b2hi) + whalf * (64 * 64);
            #pragma unroll
            for (int kt = 0; kt < 4; kt++) {
                wmma::load_matrix_sync(af, As + wrow * LDA2 + wn + kt * 16, LDA2);
                #pragma unroll
                for (int j = 0; j < 4; j++) {
                    wmma::load_matrix_sync(bf, Bg + (kt * 16) * 64 + j * 16, 64);
                    wmma::mma_sync(acc[j], af, bf, acc[j]);
                }
            }
        }
        // store C2 (float)
        #pragma unroll
        for (int j = 0; j < 4; j++)
            wmma::store_matrix_sync(cscr + wrow * LDCS + wn + j * 16, acc[j], LDCS, wmma::mem_row_major);
        __syncthreads();

        // ---- head: 4 threads per row, shfl reduce ----
        {
            const int r = tid >> 2, q = tid & 3;
            const int b = b0 + r;
            const bool rv = b < B;
            int ev = 0;
            if (rv) {
                const float* xr = x + (size_t)b * OBS;
                float x0 = xr[0], x1 = xr[1], x2 = xr[2];
                float bv = x0;
                if (x1 > bv) { ev = 1; bv = x1; }
                if (x2 > bv) ev = 2;
            }
            float lg0 = 0.f, lg1 = 0.f, lg2 = 0.f, lg3 = 0.f, lg4 = 0.f, vv = 0.f;
            const float* whp = whs + ev * (HID * NACT);
            const float* cr  = cscr + r * LDCS;
            #pragma unroll 4
            for (int c = 0; c < 16; c++) {
                int col = q * 16 + c;
                float f = tanhf(cr[col] + b2s[col]);
                const float* w = whp + col * NACT;
                lg0 += f * w[0]; lg1 += f * w[1]; lg2 += f * w[2];
                lg3 += f * w[3]; lg4 += f * w[4];
                float fc = tanhf(cr[64 + col] + b2s[64 + col]);
                vv += fc * wc3s[col];
            }
            #pragma unroll
            for (int d = 1; d <= 2; d <<= 1) {
                lg0 += __shfl_xor_sync(0xffffffffu, lg0, d);
                lg1 += __shfl_xor_sync(0xffffffffu, lg1, d);
                lg2 += __shfl_xor_sync(0xffffffffu, lg2, d);
                lg3 += __shfl_xor_sync(0xffffffffu, lg3, d);
                lg4 += __shfl_xor_sync(0xffffffffu, lg4, d);
                vv  += __shfl_xor_sync(0xffffffffu, vv, d);
            }
            if (q == 0 && rv) {
                const float* bhp = bhs + ev * NACT;
                lg0 += bhp[0]; lg1 += bhp[1]; lg2 += bhp[2]; lg3 += bhp[3]; lg4 += bhp[4];
                float m = fmaxf(fmaxf(fmaxf(lg0, lg1), fmaxf(lg2, lg3)), lg4);
                float e0 = expf(lg0 - m), e1 = expf(lg1 - m), e2 = expf(lg2 - m);
                float e3 = expf(lg3 - m), e4 = expf(lg4 - m);
                float lse = logf(e0 + e1 + e2 + e3 + e4);
                float p0 = lg0 - m - lse, p1 = lg1 - m - lse, p2 = lg2 - m - lse;
                float p3 = lg3 - m - lse, p4 = lg4 - m - lse;
                float ent = -(expf(p0) * p0 + expf(p1) * p1 + expf(p2) * p2
                              + expf(p3) * p3 + expf(p4) * p4);
                int act = action[b];
                float logp = (act == 0) ? p0 : (act == 1) ? p1 : (act == 2) ? p2
                           : (act == 3) ? p3 : p4;
                out[b]                 = (float)act;
                out[(size_t)B + b]     = logp;
                out[(size_t)2 * B + b] = ent;
                out[(size_t)3 * B + b] = vv + bc3s[0];
            }
        }
        // next tile's staging sync (loop top) orders cscr/xa reuse
    }
}

extern "C" void kernel_launch(void* const* d_in, const int* in_sizes, int n_in,
                              void* d_out, int out_size)
{
    const float* x      = (const float*)d_in[0];
    const int*   action = (const int*)  d_in[1];
    const float* W1     = (const float*)d_in[2];
    const float* b1     = (const float*)d_in[3];
    const float* W2     = (const float*)d_in[4];
    const float* b2     = (const float*)d_in[5];
    const float* Wh     = (const float*)d_in[6];
    const float* bh     = (const float*)d_in[7];
    const float* Wc1    = (const float*)d_in[8];
    const float* bc1    = (const float*)d_in[9];
    const float* Wc2    = (const float*)d_in[10];
    const float* bc2    = (const float*)d_in[11];
    const float* Wc3    = (const float*)d_in[12];
    const float* bc3    = (const float*)d_in[13];
    float* out = (float*)d_out;

    const int B = in_sizes[1];
    const int ntiles = (B + TM - 1) / TM;
    (void)n_in; (void)out_size;

    wconv_kernel<<<52, 256>>>(W1, Wc1, W2, Wc2);

    cudaFuncSetAttribute(agent_pers_kernel,
                         cudaFuncAttributeMaxDynamicSharedMemorySize, SMEM_BYTES);
    agent_pers_kernel<<<GRID, NTHR, SMEM_BYTES>>>(
        x, action, b1, b2, Wh, bh, bc1, bc2, Wc3, bc3, out, B, ntiles);
}